// round 12
// baseline (speedup 1.0000x reference)
#include <cuda_runtime.h>
#include <cuda_bf16.h>
#include <stdint.h>
#include <math.h>

// Shapes
#define BATCH 32
#define NTURN 20
#define JTOK  64
#define LSEQ  256
#define DDIM  512
#define NJ    1280
#define MROWS 8192
#define NEGV  (-4294967295.0f)

// Compact split scratch (hi/lo)
__device__ __align__(16) __nv_bfloat16 g_Khi [(size_t)BATCH*LSEQ*DDIM];
__device__ __align__(16) __nv_bfloat16 g_Klo [(size_t)BATCH*LSEQ*DDIM];
__device__ __align__(16) __nv_bfloat16 g_Qhi [(size_t)BATCH*NJ*DDIM];
__device__ __align__(16) __nv_bfloat16 g_Qlo [(size_t)BATCH*NJ*DDIM];
__device__ __align__(16) __nv_bfloat16 g_Qthi[(size_t)BATCH*DDIM*NJ];   // transposed [b][d][j]
__device__ __align__(16) __nv_bfloat16 g_Qtlo[(size_t)BATCH*DDIM*NJ];
__device__ __align__(16) float         g_S   [(size_t)BATCH*LSEQ*NJ];
__device__ __align__(16) __nv_bfloat16 g_Chi [(size_t)BATCH*LSEQ*NJ];
__device__ __align__(16) __nv_bfloat16 g_Clo [(size_t)BATCH*LSEQ*NJ];
__device__ __align__(16) __nv_bfloat16 g_Fhi [(size_t)MROWS*1024];
__device__ __align__(16) __nv_bfloat16 g_Flo [(size_t)MROWS*1024];
__device__ __align__(16) __nv_bfloat16 g_Whi [(size_t)DDIM*1024];
__device__ __align__(16) __nv_bfloat16 g_Wlo [(size_t)DDIM*1024];

#define KEY_ELEMS ((size_t)BATCH*LSEQ*DDIM)   // 4,194,304
#define W_ELEMS   ((size_t)DDIM*1024)         //   524,288

// ---------------------------------------------------------------------------
// helpers
// ---------------------------------------------------------------------------
__device__ __forceinline__ uint32_t smem_u32(const void* p) {
    uint32_t a;
    asm("{ .reg .u64 t; cvta.to.shared.u64 t, %1; cvt.u32.u64 %0, t; }" : "=r"(a) : "l"(p));
    return a;
}
__device__ __forceinline__ void split_bf(float x, __nv_bfloat16& h, __nv_bfloat16& l) {
    h = __float2bfloat16(x);
    l = __float2bfloat16(x - __bfloat162float(h));
}
__device__ __forceinline__ void cpa16(uint32_t saddr, const void* g) {
    asm volatile("cp.async.cg.shared.global.L2::256B [%0], [%1], 16;" :: "r"(saddr), "l"(g));
}
#define CP_COMMIT() asm volatile("cp.async.commit_group;")
#define CP_WAIT0()  asm volatile("cp.async.wait_group 0;")

#define LDSM4(R, ADDR) \
    asm volatile("ldmatrix.sync.aligned.m8n8.x4.shared.b16 {%0,%1,%2,%3}, [%4];" \
        : "=r"((R)[0]), "=r"((R)[1]), "=r"((R)[2]), "=r"((R)[3]) : "r"(ADDR))

#define MMA16816(C, A, B0, B1) \
    asm volatile("mma.sync.aligned.m16n8k16.row.col.f32.bf16.bf16.f32 " \
        "{%0,%1,%2,%3},{%4,%5,%6,%7},{%8,%9},{%0,%1,%2,%3};" \
        : "+f"((C)[0]), "+f"((C)[1]), "+f"((C)[2]), "+f"((C)[3]) \
        : "r"((A)[0]), "r"((A)[1]), "r"((A)[2]), "r"((A)[3]), "r"(B0), "r"(B1))

// smem: 2 stages x 4 tiles (A_hi, A_lo, B_hi, B_lo); tile = 128 rows x 32 K-cols
#define PITCH 40
#define TILE  (128 * PITCH * 2)           // 10240 B
#define STG   (4 * TILE)                  // 40960 B per stage
#define SMEM_BYTES (2 * STG)              // 81920 B (2 CTAs/SM = 160KB)

// ---------------------------------------------------------------------------
// load one K=32 chunk: 4 tiles (A_hi, A_lo, B_hi, B_lo)
// ---------------------------------------------------------------------------
__device__ __forceinline__ void load_tiles4(uint32_t sb, int stage,
                                            const __nv_bfloat16* Ah, const __nv_bfloat16* Al, int lda,
                                            const __nv_bfloat16* Bh, const __nv_bfloat16* Bl, int ldb,
                                            int koff)
{
    const int tid = threadIdx.x;
    const uint32_t s0 = sb + stage * STG;
    #pragma unroll
    for (int i = 0; i < 2; ++i) {
        int id = tid + i * 256;
        int r = id >> 2, cc = id & 3;
        uint32_t so = (uint32_t)(r * PITCH + cc * 8) * 2;
        size_t goA = (size_t)r * lda + koff + cc * 8;
        size_t goB = (size_t)r * ldb + koff + cc * 8;
        cpa16(s0 + so,            Ah + goA);
        cpa16(s0 + TILE + so,     Al + goA);
        cpa16(s0 + 2 * TILE + so, Bh + goB);
        cpa16(s0 + 3 * TILE + so, Bl + goB);
    }
}

// per K=32 chunk: 2 k16 steps; per mt: load a_hi/a_lo frags, then issue the
// three products in separate nt-sweeps so same-accumulator MMAs are 4 apart.
__device__ __forceinline__ void hmma_compute4(uint32_t sb, int stage,
                                              int lane, int wm0, int wn0,
                                              float acc[4][4][4])
{
    const uint32_t sAh = sb + stage * STG;
    const uint32_t sAl = sAh + TILE;
    const uint32_t sBh = sAh + 2 * TILE;
    const uint32_t sBl = sAh + 3 * TILE;
    const int rowoff = lane & 15;
    #pragma unroll
    for (int ks = 0; ks < 2; ++ks) {
        const int coloff = ks * 16 + (lane >> 4) * 8;
        uint32_t bh[2][4], blo[2][4];
        #pragma unroll
        for (int np = 0; np < 2; ++np) {
            uint32_t bo = (uint32_t)((wn0 + np * 16 + rowoff) * PITCH + coloff) * 2;
            LDSM4(bh[np],  sBh + bo);
            LDSM4(blo[np], sBl + bo);
        }
        #pragma unroll
        for (int mt = 0; mt < 4; ++mt) {
            uint32_t ah[4], al[4];
            uint32_t ao = (uint32_t)((wm0 + mt * 16 + rowoff) * PITCH + coloff) * 2;
            LDSM4(ah, sAh + ao);
            LDSM4(al, sAl + ao);
            #pragma unroll
            for (int nt = 0; nt < 4; ++nt)
                MMA16816(acc[mt][nt], ah, bh[nt >> 1][nt & 1],  bh[nt >> 1][2 + (nt & 1)]);
            #pragma unroll
            for (int nt = 0; nt < 4; ++nt)
                MMA16816(acc[mt][nt], ah, blo[nt >> 1][nt & 1], blo[nt >> 1][2 + (nt & 1)]);
            #pragma unroll
            for (int nt = 0; nt < 4; ++nt)
                MMA16816(acc[mt][nt], al, bh[nt >> 1][nt & 1],  bh[nt >> 1][2 + (nt & 1)]);
        }
    }
}

// 2-stage pipelined mainloop over bl K=32 chunks; one __syncthreads per chunk.
__device__ __forceinline__ void hmma_loop4(char* smem,
                                           const __nv_bfloat16* Ahi, const __nv_bfloat16* Alo, int lda,
                                           const __nv_bfloat16* Bhi, const __nv_bfloat16* Blo, int ldb,
                                           int bl, float acc[4][4][4])
{
    const int tid = threadIdx.x;
    const int lane = tid & 31, wid = tid >> 5;
    const int wm0 = (wid >> 2) * 64, wn0 = (wid & 3) * 32;
    const uint32_t sb = smem_u32(smem);

    load_tiles4(sb, 0, Ahi, Alo, lda, Bhi, Blo, ldb, 0);
    CP_COMMIT();

    for (int c = 0; c < bl; ++c) {
        CP_WAIT0();
        __syncthreads();
        if (c + 1 < bl) {
            load_tiles4(sb, (c + 1) & 1, Ahi, Alo, lda, Bhi, Blo, ldb, (c + 1) * 32);
            CP_COMMIT();
        }
        hmma_compute4(sb, c & 1, lane, wm0, wn0, acc);
    }
}

// ---------------------------------------------------------------------------
// Conversion kernels (fp32 -> compact hi/lo bf16)
// ---------------------------------------------------------------------------
__device__ __forceinline__ void split4_store(const float4 v, __nv_bfloat16* hi, __nv_bfloat16* lo, size_t o)
{
    __nv_bfloat16 h[4], l[4];
    split_bf(v.x, h[0], l[0]); split_bf(v.y, h[1], l[1]);
    split_bf(v.z, h[2], l[2]); split_bf(v.w, h[3], l[3]);
    __nv_bfloat162 hh0, hh1, ll0, ll1;
    hh0.x = h[0]; hh0.y = h[1]; hh1.x = h[2]; hh1.y = h[3];
    ll0.x = l[0]; ll0.y = l[1]; ll1.x = l[2]; ll1.y = l[3];
    *(__nv_bfloat162*)(hi + o) = hh0; *(__nv_bfloat162*)(hi + o + 2) = hh1;
    *(__nv_bfloat162*)(lo + o) = ll0; *(__nv_bfloat162*)(lo + o + 2) = ll1;
}

// keys + W split in one kernel (flat index over both tensors / 4 elems)
__global__ __launch_bounds__(256) void conv_kw(const float* __restrict__ keys,
                                               const float* __restrict__ Wm)
{
    size_t t = (size_t)blockIdx.x * 256 + threadIdx.x;   // 0 .. (KEY+W)/4-1
    size_t o = t * 4;
    if (o < KEY_ELEMS) {
        split4_store(*(const float4*)(keys + o), g_Khi, g_Klo, o);
    } else {
        size_t ow = o - KEY_ELEMS;
        split4_store(*(const float4*)(Wm + ow), g_Whi, g_Wlo, ow);
    }
}

// Merged split + transpose: q[b][j][d] -> Q{hi,lo}[b][j][d] AND Qt{hi,lo}[b][d][j].
__global__ __launch_bounds__(256) void conv_qt(const float* __restrict__ q)
{
    __shared__ __nv_bfloat16 shh[32][72];
    __shared__ __nv_bfloat16 shl[32][72];
    const int b  = blockIdx.z;
    const int d0 = blockIdx.y * 32;
    const int j0 = blockIdx.x * 64;
    const int t  = threadIdx.x;

    #pragma unroll
    for (int i = 0; i < 2; ++i) {
        int jj = (t >> 3) + i * 32;               // 0..63
        int dd = (t & 7) * 4;                     // 0..28
        size_t qo = ((size_t)b * NJ + j0 + jj) * DDIM + d0 + dd;
        float4 v = *(const float4*)(q + qo);
        __nv_bfloat16 h0, l0, h1, l1, h2, l2, h3, l3;
        split_bf(v.x, h0, l0); split_bf(v.y, h1, l1);
        split_bf(v.z, h2, l2); split_bf(v.w, h3, l3);
        __nv_bfloat162 hp0, hp1, lp0, lp1;
        hp0.x = h0; hp0.y = h1; hp1.x = h2; hp1.y = h3;
        lp0.x = l0; lp0.y = l1; lp1.x = l2; lp1.y = l3;
        *(__nv_bfloat162*)(g_Qhi + qo)     = hp0; *(__nv_bfloat162*)(g_Qhi + qo + 2) = hp1;
        *(__nv_bfloat162*)(g_Qlo + qo)     = lp0; *(__nv_bfloat162*)(g_Qlo + qo + 2) = lp1;
        shh[dd+0][jj] = h0; shl[dd+0][jj] = l0;
        shh[dd+1][jj] = h1; shl[dd+1][jj] = l1;
        shh[dd+2][jj] = h2; shl[dd+2][jj] = l2;
        shh[dd+3][jj] = h3; shl[dd+3][jj] = l3;
    }
    __syncthreads();

    const int r  = t >> 3;                        // 0..31 (d row)
    const int pc = t & 7;                         // 8 bf16 = 16B chunk
    size_t o = ((size_t)b * DDIM + d0 + r) * NJ + j0 + pc * 8;
    *(uint4*)(g_Qthi + o) = *(const uint4*)&shh[r][pc * 8];
    *(uint4*)(g_Qtlo + o) = *(const uint4*)&shl[r][pc * 8];
}

// ---------------------------------------------------------------------------
// GEMM1: scores[b] = keys x queries^T  (M=256, N=1280, K=512) -> g_S
// ---------------------------------------------------------------------------
__global__ __launch_bounds__(256, 2) void k_hm1()
{
    extern __shared__ char smem[];
    const int b = blockIdx.z, m0 = blockIdx.y * 128, n0 = blockIdx.x * 128;
    const __nv_bfloat16* Ah = g_Khi + ((size_t)b * LSEQ + m0) * DDIM;
    const __nv_bfloat16* Al = g_Klo + ((size_t)b * LSEQ + m0) * DDIM;
    const __nv_bfloat16* Bh = g_Qhi + ((size_t)b * NJ + n0) * DDIM;
    const __nv_bfloat16* Bl = g_Qlo + ((size_t)b * NJ + n0) * DDIM;
    float acc[4][4][4] = {};
    hmma_loop4(smem, Ah, Al, DDIM, Bh, Bl, DDIM, DDIM / 32, acc);

    const int lane = threadIdx.x & 31, wid = threadIdx.x >> 5;
    const int wm0 = (wid >> 2) * 64, wn0 = (wid & 3) * 32;
    float* C = g_S + (size_t)b * LSEQ * NJ;
    #pragma unroll
    for (int mt = 0; mt < 4; ++mt)
        #pragma unroll
        for (int nt = 0; nt < 4; ++nt)
            #pragma unroll
            for (int rh = 0; rh < 2; ++rh) {
                int m = m0 + wm0 + mt * 16 + (lane >> 2) + rh * 8;
                int n = n0 + wn0 + nt * 8 + (lane & 3) * 2;
                *(float2*)(C + (size_t)m * NJ + n) =
                    make_float2(acc[mt][nt][rh * 2], acc[mt][nt][rh * 2 + 1]);
            }
}

// ---------------------------------------------------------------------------
// Softmax + combined weights -> g_Chi / g_Clo
// ---------------------------------------------------------------------------
__global__ __launch_bounds__(256) void k_softmax(const float* __restrict__ qmask,
                                                 const float* __restrict__ kmask)
{
    const int row = blockIdx.x;
    const int b   = row >> 8;

    __shared__ float buf[NJ];
    __shared__ float qm[NJ];
    __shared__ float sim2[32];
    __shared__ float tvalid[32];
    __shared__ float wn[NTURN];

    const int tid = threadIdx.x;
    const float* srow = g_S + (size_t)row * NJ;
    const float* qmrow = qmask + b * NJ;

    for (int j = tid; j < NJ; j += 256) { buf[j] = srow[j]; qm[j] = qmrow[j]; }
    __syncthreads();

    const int wid = tid >> 5, lane = tid & 31;
    for (int n = wid; n < NTURN; n += 8) {
        const int base = n * JTOK;
        float q1 = qm[base + lane],  q2 = qm[base + 32 + lane];
        float s1 = buf[base + lane], s2 = buf[base + 32 + lane];
        float x1 = (q1 == 0.0f) ? NEGV : s1;
        float x2 = (q2 == 0.0f) ? NEGV : s2;
        float mx = fmaxf(x1, x2);
        #pragma unroll
        for (int o = 16; o; o >>= 1) mx = fmaxf(mx, __shfl_xor_sync(0xFFFFFFFFu, mx, o));
        float e1 = __expf(x1 - mx), e2 = __expf(x2 - mx);
        float es = e1 + e2, qs = q1 + q2, sp = e1 * s1 + e2 * s2;
        #pragma unroll
        for (int o = 16; o; o >>= 1) {
            es += __shfl_xor_sync(0xFFFFFFFFu, es, o);
            qs += __shfl_xor_sync(0xFFFFFFFFu, qs, o);
            sp += __shfl_xor_sync(0xFFFFFFFFu, sp, o);
        }
        float inv = 1.0f / es;
        buf[base + lane]      = e1 * inv;
        buf[base + 32 + lane] = e2 * inv;
        if (lane == 0) { sim2[n] = sp * inv; tvalid[n] = qs; }
    }
    __syncthreads();

    if (wid == 0) {
        float v = (lane < NTURN && tvalid[lane] != 0.0f) ? sim2[lane] : NEGV;
        float mx = v;
        #pragma unroll
        for (int o = 16; o; o >>= 1) mx = fmaxf(mx, __shfl_xor_sync(0xFFFFFFFFu, mx, o));
        float e = (lane < NTURN) ? __expf(v - mx) : 0.0f;
        float es = e;
        #pragma unroll
        for (int o = 16; o; o >>= 1) es += __shfl_xor_sync(0xFFFFFFFFu, es, o);
        if (lane < NTURN) wn[lane] = e / es;
    }
    __syncthreads();

    const float m = kmask[row];
    for (int idx = tid; idx < NJ; idx += 256) {
        const int n = idx >> 6;
        float c = m * wn[n] * buf[idx];
        __nv_bfloat16 h, l; split_bf(c, h, l);
        g_Chi[(size_t)row * NJ + idx] = h;
        g_Clo[(size_t)row * NJ + idx] = l;
    }
}

// ---------------------------------------------------------------------------
// GEMM2: attn[b] = C x queries (M=256, N=512, K=1280) -> g_Fhi/g_Flo
// ---------------------------------------------------------------------------
__global__ __launch_bounds__(256, 2) void k_hm2(const float* __restrict__ keys)
{
    extern __shared__ char smem[];
    const int b = blockIdx.z, m0 = blockIdx.y * 128, n0 = blockIdx.x * 128;
    const __nv_bfloat16* Ah = g_Chi  + ((size_t)b * LSEQ + m0) * NJ;
    const __nv_bfloat16* Al = g_Clo  + ((size_t)b * LSEQ + m0) * NJ;
    const __nv_bfloat16* Bh = g_Qthi + ((size_t)b * DDIM + n0) * NJ;
    const __nv_bfloat16* Bl = g_Qtlo + ((size_t)b * DDIM + n0) * NJ;
    float acc[4][4][4] = {};
    hmma_loop4(smem, Ah, Al, NJ, Bh, Bl, NJ, NJ / 32, acc);

    const int lane = threadIdx.x & 31, wid = threadIdx.x >> 5;
    const int wm0 = (wid >> 2) * 64, wn0 = (wid & 3) * 32;
    const float* keyb = keys + (size_t)b * LSEQ * DDIM;
    #pragma unroll
    for (int mt = 0; mt < 4; ++mt)
        #pragma unroll
        for (int nt = 0; nt < 4; ++nt)
            #pragma unroll
            for (int rh = 0; rh < 2; ++rh) {
                int m = m0 + wm0 + mt * 16 + (lane >> 2) + rh * 8;
                int n = n0 + wn0 + nt * 8 + (lane & 3) * 2;
                float a0 = acc[mt][nt][rh * 2], a1 = acc[mt][nt][rh * 2 + 1];
                float2 kv = *(const float2*)(keyb + (size_t)m * DDIM + n);
                float mu0 = a0 * kv.x, mu1 = a1 * kv.y;
                float df0 = a0 - kv.x, df1 = a1 - kv.y;
                float sq0 = df0 * df0, sq1 = df1 * df1;
                size_t rowo = ((size_t)b * LSEQ + m) * 1024;
                __nv_bfloat16 h0, l0, h1, l1;
                __nv_bfloat162 hp, lp;
                split_bf(mu0, h0, l0); split_bf(mu1, h1, l1);
                hp.x = h0; hp.y = h1; lp.x = l0; lp.y = l1;
                *(__nv_bfloat162*)(g_Fhi + rowo + n) = hp;
                *(__nv_bfloat162*)(g_Flo + rowo + n) = lp;
                split_bf(sq0, h0, l0); split_bf(sq1, h1, l1);
                hp.x = h0; hp.y = h1; lp.x = l0; lp.y = l1;
                *(__nv_bfloat162*)(g_Fhi + rowo + 512 + n) = hp;
                *(__nv_bfloat162*)(g_Flo + rowo + 512 + n) = lp;
            }
}

// ---------------------------------------------------------------------------
// GEMM3: out = relu(F x W^T + b)  (M=8192, N=512, K=1024)
// ---------------------------------------------------------------------------
__global__ __launch_bounds__(256, 2) void k_hm3(const float* __restrict__ bias,
                                                float* __restrict__ out)
{
    extern __shared__ char smem[];
    const int m0 = blockIdx.y * 128, n0 = blockIdx.x * 128;
    const __nv_bfloat16* Ah = g_Fhi + (size_t)m0 * 1024;
    const __nv_bfloat16* Al = g_Flo + (size_t)m0 * 1024;
    const __nv_bfloat16* Bh = g_Whi + (size_t)n0 * 1024;
    const __nv_bfloat16* Bl = g_Wlo + (size_t)n0 * 1024;
    float acc[4][4][4] = {};
    hmma_loop4(smem, Ah, Al, 1024, Bh, Bl, 1024, 1024 / 32, acc);

    const int lane = threadIdx.x & 31, wid = threadIdx.x >> 5;
    const int wm0 = (wid >> 2) * 64, wn0 = (wid & 3) * 32;
    #pragma unroll
    for (int mt = 0; mt < 4; ++mt)
        #pragma unroll
        for (int nt = 0; nt < 4; ++nt)
            #pragma unroll
            for (int rh = 0; rh < 2; ++rh) {
                int m = m0 + wm0 + mt * 16 + (lane >> 2) + rh * 8;
                int n = n0 + wn0 + nt * 8 + (lane & 3) * 2;
                float2 bb = *(const float2*)(bias + n);
                float v0 = fmaxf(acc[mt][nt][rh * 2]     + bb.x, 0.0f);
                float v1 = fmaxf(acc[mt][nt][rh * 2 + 1] + bb.y, 0.0f);
                *(float2*)(out + (size_t)m * DDIM + n) = make_float2(v0, v1);
            }
}

// ---------------------------------------------------------------------------
extern "C" void kernel_launch(void* const* d_in, const int* in_sizes, int n_in,
                              void* d_out, int out_size)
{
    const float* queries = (const float*)d_in[0];  // [32,20,64,512]
    const float* keys    = (const float*)d_in[1];  // [32,256,512]
    const float* qmask   = (const float*)d_in[2];  // [32,20,64]
    const float* kmask   = (const float*)d_in[3];  // [32,256]
    const float* Wm      = (const float*)d_in[4];  // [512,1024]
    const float* bias    = (const float*)d_in[5];  // [512]
    float* out = (float*)d_out;                    // [32,256,512]

    cudaFuncSetAttribute(k_hm1, cudaFuncAttributeMaxDynamicSharedMemorySize, SMEM_BYTES);
    cudaFuncSetAttribute(k_hm2, cudaFuncAttributeMaxDynamicSharedMemorySize, SMEM_BYTES);
    cudaFuncSetAttribute(k_hm3, cudaFuncAttributeMaxDynamicSharedMemorySize, SMEM_BYTES);

    conv_kw<<<(int)((KEY_ELEMS + W_ELEMS) / 4 / 256), 256>>>(keys, Wm);
    conv_qt<<<dim3(NJ / 64, DDIM / 32, BATCH), 256>>>(queries);

    k_hm1<<<dim3(NJ / 128, LSEQ / 128, BATCH), 256, SMEM_BYTES>>>();
    k_softmax<<<MROWS, 256>>>(qmask, kmask);
    k_hm2<<<dim3(DDIM / 128, LSEQ / 128, BATCH), 256, SMEM_BYTES>>>(keys);
    k_hm3<<<dim3(DDIM / 128, MROWS / 128, 1), 256, SMEM_BYTES>>>(bias, out);
}

// round 13
// speedup vs baseline: 1.0337x; 1.0337x over previous
#include <cuda_runtime.h>
#include <cuda_bf16.h>
#include <stdint.h>
#include <math.h>

// Shapes
#define BATCH 32
#define NTURN 20
#define JTOK  64
#define LSEQ  256
#define DDIM  512
#define NJ    1280
#define MROWS 8192
#define NEGV  (-4294967295.0f)

// Compact split scratch (hi/lo)
__device__ __align__(16) __nv_bfloat16 g_Khi [(size_t)BATCH*LSEQ*DDIM];
__device__ __align__(16) __nv_bfloat16 g_Klo [(size_t)BATCH*LSEQ*DDIM];
__device__ __align__(16) __nv_bfloat16 g_Qhi [(size_t)BATCH*NJ*DDIM];
__device__ __align__(16) __nv_bfloat16 g_Qlo [(size_t)BATCH*NJ*DDIM];
__device__ __align__(16) __nv_bfloat16 g_Qthi[(size_t)BATCH*DDIM*NJ];   // transposed [b][d][j]
__device__ __align__(16) __nv_bfloat16 g_Qtlo[(size_t)BATCH*DDIM*NJ];
__device__ __align__(16) float         g_S   [(size_t)BATCH*LSEQ*NJ];
__device__ __align__(16) __nv_bfloat16 g_Chi [(size_t)BATCH*LSEQ*NJ];
__device__ __align__(16) __nv_bfloat16 g_Clo [(size_t)BATCH*LSEQ*NJ];
__device__ __align__(16) __nv_bfloat16 g_Fhi [(size_t)MROWS*1024];
__device__ __align__(16) __nv_bfloat16 g_Flo [(size_t)MROWS*1024];
__device__ __align__(16) __nv_bfloat16 g_Whi [(size_t)DDIM*1024];
__device__ __align__(16) __nv_bfloat16 g_Wlo [(size_t)DDIM*1024];

#define KEY_ELEMS ((size_t)BATCH*LSEQ*DDIM)   // 4,194,304
#define W_ELEMS   ((size_t)DDIM*1024)         //   524,288

// ---------------------------------------------------------------------------
// helpers
// ---------------------------------------------------------------------------
__device__ __forceinline__ uint32_t smem_u32(const void* p) {
    uint32_t a;
    asm("{ .reg .u64 t; cvta.to.shared.u64 t, %1; cvt.u32.u64 %0, t; }" : "=r"(a) : "l"(p));
    return a;
}
__device__ __forceinline__ void split_bf(float x, __nv_bfloat16& h, __nv_bfloat16& l) {
    h = __float2bfloat16(x);
    l = __float2bfloat16(x - __bfloat162float(h));
}
__device__ __forceinline__ void cpa16(uint32_t saddr, const void* g) {
    asm volatile("cp.async.cg.shared.global [%0], [%1], 16;" :: "r"(saddr), "l"(g));
}
#define CP_COMMIT() asm volatile("cp.async.commit_group;")
#define CP_WAIT0()  asm volatile("cp.async.wait_group 0;")

#define LDSM4(R, ADDR) \
    asm volatile("ldmatrix.sync.aligned.m8n8.x4.shared.b16 {%0,%1,%2,%3}, [%4];" \
        : "=r"((R)[0]), "=r"((R)[1]), "=r"((R)[2]), "=r"((R)[3]) : "r"(ADDR))

#define MMA16816(C, A, B0, B1) \
    asm volatile("mma.sync.aligned.m16n8k16.row.col.f32.bf16.bf16.f32 " \
        "{%0,%1,%2,%3},{%4,%5,%6,%7},{%8,%9},{%0,%1,%2,%3};" \
        : "+f"((C)[0]), "+f"((C)[1]), "+f"((C)[2]), "+f"((C)[3]) \
        : "r"((A)[0]), "r"((A)[1]), "r"((A)[2]), "r"((A)[3]), "r"(B0), "r"(B1))

// smem: 2 stages x 4 tiles (A_hi, A_lo, B_hi, B_lo); tile = 128 rows x 32 K-cols
#define PITCH 40
#define TILE  (128 * PITCH * 2)           // 10240 B
#define STG   (4 * TILE)                  // 40960 B per stage
#define SMEM_BYTES (2 * STG)              // 81920 B (2 CTAs/SM = 160KB)

// ---------------------------------------------------------------------------
// load one K=32 chunk: 4 tiles (A_hi, A_lo, B_hi, B_lo)
// ---------------------------------------------------------------------------
__device__ __forceinline__ void load_tiles4(uint32_t sb, int stage,
                                            const __nv_bfloat16* Ah, const __nv_bfloat16* Al, int lda,
                                            const __nv_bfloat16* Bh, const __nv_bfloat16* Bl, int ldb,
                                            int koff)
{
    const int tid = threadIdx.x;
    const uint32_t s0 = sb + stage * STG;
    #pragma unroll
    for (int i = 0; i < 2; ++i) {
        int id = tid + i * 256;
        int r = id >> 2, cc = id & 3;
        uint32_t so = (uint32_t)(r * PITCH + cc * 8) * 2;
        size_t goA = (size_t)r * lda + koff + cc * 8;
        size_t goB = (size_t)r * ldb + koff + cc * 8;
        cpa16(s0 + so,            Ah + goA);
        cpa16(s0 + TILE + so,     Al + goA);
        cpa16(s0 + 2 * TILE + so, Bh + goB);
        cpa16(s0 + 3 * TILE + so, Bl + goB);
    }
}

// per K=32 chunk: 2 k16 steps; per mt: load a_hi/a_lo frags, then issue the
// three products in separate nt-sweeps so same-accumulator MMAs are 4 apart.
__device__ __forceinline__ void hmma_compute4(uint32_t sb, int stage,
                                              int lane, int wm0, int wn0,
                                              float acc[4][4][4])
{
    const uint32_t sAh = sb + stage * STG;
    const uint32_t sAl = sAh + TILE;
    const uint32_t sBh = sAh + 2 * TILE;
    const uint32_t sBl = sAh + 3 * TILE;
    const int rowoff = lane & 15;
    #pragma unroll
    for (int ks = 0; ks < 2; ++ks) {
        const int coloff = ks * 16 + (lane >> 4) * 8;
        uint32_t bh[2][4], blo[2][4];
        #pragma unroll
        for (int np = 0; np < 2; ++np) {
            uint32_t bo = (uint32_t)((wn0 + np * 16 + rowoff) * PITCH + coloff) * 2;
            LDSM4(bh[np],  sBh + bo);
            LDSM4(blo[np], sBl + bo);
        }
        #pragma unroll
        for (int mt = 0; mt < 4; ++mt) {
            uint32_t ah[4], al[4];
            uint32_t ao = (uint32_t)((wm0 + mt * 16 + rowoff) * PITCH + coloff) * 2;
            LDSM4(ah, sAh + ao);
            LDSM4(al, sAl + ao);
            #pragma unroll
            for (int nt = 0; nt < 4; ++nt)
                MMA16816(acc[mt][nt], ah, bh[nt >> 1][nt & 1],  bh[nt >> 1][2 + (nt & 1)]);
            #pragma unroll
            for (int nt = 0; nt < 4; ++nt)
                MMA16816(acc[mt][nt], ah, blo[nt >> 1][nt & 1], blo[nt >> 1][2 + (nt & 1)]);
            #pragma unroll
            for (int nt = 0; nt < 4; ++nt)
                MMA16816(acc[mt][nt], al, bh[nt >> 1][nt & 1],  bh[nt >> 1][2 + (nt & 1)]);
        }
    }
}

// 2-stage pipelined mainloop over bl K=32 chunks; one __syncthreads per chunk.
__device__ __forceinline__ void hmma_loop4(char* smem,
                                           const __nv_bfloat16* Ahi, const __nv_bfloat16* Alo, int lda,
                                           const __nv_bfloat16* Bhi, const __nv_bfloat16* Blo, int ldb,
                                           int bl, float acc[4][4][4])
{
    const int tid = threadIdx.x;
    const int lane = tid & 31, wid = tid >> 5;
    const int wm0 = (wid >> 2) * 64, wn0 = (wid & 3) * 32;
    const uint32_t sb = smem_u32(smem);

    load_tiles4(sb, 0, Ahi, Alo, lda, Bhi, Blo, ldb, 0);
    CP_COMMIT();

    for (int c = 0; c < bl; ++c) {
        CP_WAIT0();
        __syncthreads();
        if (c + 1 < bl) {
            load_tiles4(sb, (c + 1) & 1, Ahi, Alo, lda, Bhi, Blo, ldb, (c + 1) * 32);
            CP_COMMIT();
        }
        hmma_compute4(sb, c & 1, lane, wm0, wn0, acc);
    }
}

// ---------------------------------------------------------------------------
// Conversion kernels (fp32 -> compact hi/lo bf16)
// ---------------------------------------------------------------------------
__device__ __forceinline__ void split4_store(const float4 v, __nv_bfloat16* hi, __nv_bfloat16* lo, size_t o)
{
    __nv_bfloat16 h[4], l[4];
    split_bf(v.x, h[0], l[0]); split_bf(v.y, h[1], l[1]);
    split_bf(v.z, h[2], l[2]); split_bf(v.w, h[3], l[3]);
    __nv_bfloat162 hh0, hh1, ll0, ll1;
    hh0.x = h[0]; hh0.y = h[1]; hh1.x = h[2]; hh1.y = h[3];
    ll0.x = l[0]; ll0.y = l[1]; ll1.x = l[2]; ll1.y = l[3];
    *(__nv_bfloat162*)(hi + o) = hh0; *(__nv_bfloat162*)(hi + o + 2) = hh1;
    *(__nv_bfloat162*)(lo + o) = ll0; *(__nv_bfloat162*)(lo + o + 2) = ll1;
}

// keys + W split in one kernel (flat index over both tensors / 4 elems)
__global__ __launch_bounds__(256) void conv_kw(const float* __restrict__ keys,
                                               const float* __restrict__ Wm)
{
    size_t t = (size_t)blockIdx.x * 256 + threadIdx.x;
    size_t o = t * 4;
    if (o < KEY_ELEMS) {
        split4_store(*(const float4*)(keys + o), g_Khi, g_Klo, o);
    } else {
        size_t ow = o - KEY_ELEMS;
        split4_store(*(const float4*)(Wm + ow), g_Whi, g_Wlo, ow);
    }
}

// Merged split + transpose: q[b][j][d] -> Q{hi,lo}[b][j][d] AND Qt{hi,lo}[b][d][j].
__global__ __launch_bounds__(256) void conv_qt(const float* __restrict__ q)
{
    __shared__ __nv_bfloat16 shh[32][72];
    __shared__ __nv_bfloat16 shl[32][72];
    const int b  = blockIdx.z;
    const int d0 = blockIdx.y * 32;
    const int j0 = blockIdx.x * 64;
    const int t  = threadIdx.x;

    #pragma unroll
    for (int i = 0; i < 2; ++i) {
        int jj = (t >> 3) + i * 32;               // 0..63
        int dd = (t & 7) * 4;                     // 0..28
        size_t qo = ((size_t)b * NJ + j0 + jj) * DDIM + d0 + dd;
        float4 v = *(const float4*)(q + qo);
        __nv_bfloat16 h0, l0, h1, l1, h2, l2, h3, l3;
        split_bf(v.x, h0, l0); split_bf(v.y, h1, l1);
        split_bf(v.z, h2, l2); split_bf(v.w, h3, l3);
        __nv_bfloat162 hp0, hp1, lp0, lp1;
        hp0.x = h0; hp0.y = h1; hp1.x = h2; hp1.y = h3;
        lp0.x = l0; lp0.y = l1; lp1.x = l2; lp1.y = l3;
        *(__nv_bfloat162*)(g_Qhi + qo)     = hp0; *(__nv_bfloat162*)(g_Qhi + qo + 2) = hp1;
        *(__nv_bfloat162*)(g_Qlo + qo)     = lp0; *(__nv_bfloat162*)(g_Qlo + qo + 2) = lp1;
        shh[dd+0][jj] = h0; shl[dd+0][jj] = l0;
        shh[dd+1][jj] = h1; shl[dd+1][jj] = l1;
        shh[dd+2][jj] = h2; shl[dd+2][jj] = l2;
        shh[dd+3][jj] = h3; shl[dd+3][jj] = l3;
    }
    __syncthreads();

    const int r  = t >> 3;                        // 0..31 (d row)
    const int pc = t & 7;                         // 8 bf16 = 16B chunk
    size_t o = ((size_t)b * DDIM + d0 + r) * NJ + j0 + pc * 8;
    *(uint4*)(g_Qthi + o) = *(const uint4*)&shh[r][pc * 8];
    *(uint4*)(g_Qtlo + o) = *(const uint4*)&shl[r][pc * 8];
}

// ---------------------------------------------------------------------------
// GEMM1: scores[b] = keys x queries^T  (M=256, N=1280, K=512) -> g_S
// ---------------------------------------------------------------------------
__global__ __launch_bounds__(256, 2) void k_hm1()
{
    extern __shared__ char smem[];
    const int b = blockIdx.z, m0 = blockIdx.y * 128, n0 = blockIdx.x * 128;
    const __nv_bfloat16* Ah = g_Khi + ((size_t)b * LSEQ + m0) * DDIM;
    const __nv_bfloat16* Al = g_Klo + ((size_t)b * LSEQ + m0) * DDIM;
    const __nv_bfloat16* Bh = g_Qhi + ((size_t)b * NJ + n0) * DDIM;
    const __nv_bfloat16* Bl = g_Qlo + ((size_t)b * NJ + n0) * DDIM;
    float acc[4][4][4] = {};
    hmma_loop4(smem, Ah, Al, DDIM, Bh, Bl, DDIM, DDIM / 32, acc);

    const int lane = threadIdx.x & 31, wid = threadIdx.x >> 5;
    const int wm0 = (wid >> 2) * 64, wn0 = (wid & 3) * 32;
    float* C = g_S + (size_t)b * LSEQ * NJ;
    #pragma unroll
    for (int mt = 0; mt < 4; ++mt)
        #pragma unroll
        for (int nt = 0; nt < 4; ++nt)
            #pragma unroll
            for (int rh = 0; rh < 2; ++rh) {
                int m = m0 + wm0 + mt * 16 + (lane >> 2) + rh * 8;
                int n = n0 + wn0 + nt * 8 + (lane & 3) * 2;
                *(float2*)(C + (size_t)m * NJ + n) =
                    make_float2(acc[mt][nt][rh * 2], acc[mt][nt][rh * 2 + 1]);
            }
}

// ---------------------------------------------------------------------------
// Softmax + combined weights -> g_Chi / g_Clo
// 320 threads: 10 warps x 2 turns each; 4 contiguous elems per thread.
// ---------------------------------------------------------------------------
__global__ __launch_bounds__(320) void k_softmax(const float* __restrict__ qmask,
                                                 const float* __restrict__ kmask)
{
    const int row = blockIdx.x;
    const int b   = row >> 8;

    __shared__ float buf[NJ];
    __shared__ float qm[NJ];
    __shared__ float sim2[32];
    __shared__ uint32_t tvalid[32];
    __shared__ float wn[NTURN];

    const int tid = threadIdx.x;
    const float* srow = g_S + (size_t)row * NJ;
    const float* qmrow = qmask + b * NJ;

    {
        const int idx = tid * 4;
        *(float4*)&buf[idx] = *(const float4*)(srow + idx);
        *(float4*)&qm[idx]  = *(const float4*)(qmrow + idx);
    }
    __syncthreads();

    const int wid = tid >> 5, lane = tid & 31;
    #pragma unroll
    for (int rep = 0; rep < 2; ++rep) {
        const int n = wid + rep * 10;
        const int base = n * JTOK;
        float q1 = qm[base + lane],  q2 = qm[base + 32 + lane];
        float s1 = buf[base + lane], s2 = buf[base + 32 + lane];
        float x1 = (q1 == 0.0f) ? NEGV : s1;
        float x2 = (q2 == 0.0f) ? NEGV : s2;
        float mx = fmaxf(x1, x2);
        #pragma unroll
        for (int o = 16; o; o >>= 1) mx = fmaxf(mx, __shfl_xor_sync(0xFFFFFFFFu, mx, o));
        float e1 = __expf(x1 - mx), e2 = __expf(x2 - mx);
        float es = e1 + e2, sp = e1 * s1 + e2 * s2;
        #pragma unroll
        for (int o = 16; o; o >>= 1) {
            es += __shfl_xor_sync(0xFFFFFFFFu, es, o);
            sp += __shfl_xor_sync(0xFFFFFFFFu, sp, o);
        }
        uint32_t vb = __ballot_sync(0xFFFFFFFFu, (q1 != 0.0f) || (q2 != 0.0f));
        float inv = 1.0f / es;
        buf[base + lane]      = e1 * inv;
        buf[base + 32 + lane] = e2 * inv;
        if (lane == 0) { sim2[n] = sp * inv; tvalid[n] = vb; }
    }
    __syncthreads();

    if (wid == 0) {
        float v = (lane < NTURN && tvalid[lane]) ? sim2[lane] : NEGV;
        float mx = v;
        #pragma unroll
        for (int o = 16; o; o >>= 1) mx = fmaxf(mx, __shfl_xor_sync(0xFFFFFFFFu, mx, o));
        float e = (lane < NTURN) ? __expf(v - mx) : 0.0f;
        float es = e;
        #pragma unroll
        for (int o = 16; o; o >>= 1) es += __shfl_xor_sync(0xFFFFFFFFu, es, o);
        if (lane < NTURN) wn[lane] = e / es;
    }
    __syncthreads();

    const float m = kmask[row];
    {
        const int idx = tid * 4;              // 4 elems, all in turn idx>>6
        const float w = m * wn[idx >> 6];
        float4 p = *(const float4*)&buf[idx];
        __nv_bfloat16 h0, l0, h1, l1, h2, l2, h3, l3;
        split_bf(w * p.x, h0, l0); split_bf(w * p.y, h1, l1);
        split_bf(w * p.z, h2, l2); split_bf(w * p.w, h3, l3);
        __nv_bfloat162 hp0, hp1, lp0, lp1;
        hp0.x = h0; hp0.y = h1; hp1.x = h2; hp1.y = h3;
        lp0.x = l0; lp0.y = l1; lp1.x = l2; lp1.y = l3;
        size_t o = (size_t)row * NJ + idx;
        *(__nv_bfloat162*)(g_Chi + o)     = hp0;
        *(__nv_bfloat162*)(g_Chi + o + 2) = hp1;
        *(__nv_bfloat162*)(g_Clo + o)     = lp0;
        *(__nv_bfloat162*)(g_Clo + o + 2) = lp1;
    }
}

// ---------------------------------------------------------------------------
// GEMM2: attn[b] = C x queries (M=256, N=512, K=1280) -> g_Fhi/g_Flo
// ---------------------------------------------------------------------------
__global__ __launch_bounds__(256, 2) void k_hm2(const float* __restrict__ keys)
{
    extern __shared__ char smem[];
    const int b = blockIdx.z, m0 = blockIdx.y * 128, n0 = blockIdx.x * 128;
    const __nv_bfloat16* Ah = g_Chi  + ((size_t)b * LSEQ + m0) * NJ;
    const __nv_bfloat16* Al = g_Clo  + ((size_t)b * LSEQ + m0) * NJ;
    const __nv_bfloat16* Bh = g_Qthi + ((size_t)b * DDIM + n0) * NJ;
    const __nv_bfloat16* Bl = g_Qtlo + ((size_t)b * DDIM + n0) * NJ;
    float acc[4][4][4] = {};
    hmma_loop4(smem, Ah, Al, NJ, Bh, Bl, NJ, NJ / 32, acc);

    const int lane = threadIdx.x & 31, wid = threadIdx.x >> 5;
    const int wm0 = (wid >> 2) * 64, wn0 = (wid & 3) * 32;
    const float* keyb = keys + (size_t)b * LSEQ * DDIM;
    #pragma unroll
    for (int mt = 0; mt < 4; ++mt)
        #pragma unroll
        for (int nt = 0; nt < 4; ++nt)
            #pragma unroll
            for (int rh = 0; rh < 2; ++rh) {
                int m = m0 + wm0 + mt * 16 + (lane >> 2) + rh * 8;
                int n = n0 + wn0 + nt * 8 + (lane & 3) * 2;
                float a0 = acc[mt][nt][rh * 2], a1 = acc[mt][nt][rh * 2 + 1];
                float2 kv = *(const float2*)(keyb + (size_t)m * DDIM + n);
                float mu0 = a0 * kv.x, mu1 = a1 * kv.y;
                float df0 = a0 - kv.x, df1 = a1 - kv.y;
                float sq0 = df0 * df0, sq1 = df1 * df1;
                size_t rowo = ((size_t)b * LSEQ + m) * 1024;
                __nv_bfloat16 h0, l0, h1, l1;
                __nv_bfloat162 hp, lp;
                split_bf(mu0, h0, l0); split_bf(mu1, h1, l1);
                hp.x = h0; hp.y = h1; lp.x = l0; lp.y = l1;
                *(__nv_bfloat162*)(g_Fhi + rowo + n) = hp;
                *(__nv_bfloat162*)(g_Flo + rowo + n) = lp;
                split_bf(sq0, h0, l0); split_bf(sq1, h1, l1);
                hp.x = h0; hp.y = h1; lp.x = l0; lp.y = l1;
                *(__nv_bfloat162*)(g_Fhi + rowo + 512 + n) = hp;
                *(__nv_bfloat162*)(g_Flo + rowo + 512 + n) = lp;
            }
}

// ---------------------------------------------------------------------------
// GEMM3: out = relu(F x W^T + b)  (M=8192, N=512, K=1024)
// ---------------------------------------------------------------------------
__global__ __launch_bounds__(256, 2) void k_hm3(const float* __restrict__ bias,
                                                float* __restrict__ out)
{
    extern __shared__ char smem[];
    const int m0 = blockIdx.y * 128, n0 = blockIdx.x * 128;
    const __nv_bfloat16* Ah = g_Fhi + (size_t)m0 * 1024;
    const __nv_bfloat16* Al = g_Flo + (size_t)m0 * 1024;
    const __nv_bfloat16* Bh = g_Whi + (size_t)n0 * 1024;
    const __nv_bfloat16* Bl = g_Wlo + (size_t)n0 * 1024;
    float acc[4][4][4] = {};
    hmma_loop4(smem, Ah, Al, 1024, Bh, Bl, 1024, 1024 / 32, acc);

    const int lane = threadIdx.x & 31, wid = threadIdx.x >> 5;
    const int wm0 = (wid >> 2) * 64, wn0 = (wid & 3) * 32;
    #pragma unroll
    for (int mt = 0; mt < 4; ++mt)
        #pragma unroll
        for (int nt = 0; nt < 4; ++nt)
            #pragma unroll
            for (int rh = 0; rh < 2; ++rh) {
                int m = m0 + wm0 + mt * 16 + (lane >> 2) + rh * 8;
                int n = n0 + wn0 + nt * 8 + (lane & 3) * 2;
                float2 bb = *(const float2*)(bias + n);
                float v0 = fmaxf(acc[mt][nt][rh * 2]     + bb.x, 0.0f);
                float v1 = fmaxf(acc[mt][nt][rh * 2 + 1] + bb.y, 0.0f);
                *(float2*)(out + (size_t)m * DDIM + n) = make_float2(v0, v1);
            }
}

// ---------------------------------------------------------------------------
extern "C" void kernel_launch(void* const* d_in, const int* in_sizes, int n_in,
                              void* d_out, int out_size)
{
    const float* queries = (const float*)d_in[0];  // [32,20,64,512]
    const float* keys    = (const float*)d_in[1];  // [32,256,512]
    const float* qmask   = (const float*)d_in[2];  // [32,20,64]
    const float* kmask   = (const float*)d_in[3];  // [32,256]
    const float* Wm      = (const float*)d_in[4];  // [512,1024]
    const float* bias    = (const float*)d_in[5];  // [512]
    float* out = (float*)d_out;                    // [32,256,512]

    cudaFuncSetAttribute(k_hm1, cudaFuncAttributeMaxDynamicSharedMemorySize, SMEM_BYTES);
    cudaFuncSetAttribute(k_hm2, cudaFuncAttributeMaxDynamicSharedMemorySize, SMEM_BYTES);
    cudaFuncSetAttribute(k_hm3, cudaFuncAttributeMaxDynamicSharedMemorySize, SMEM_BYTES);

    conv_kw<<<(int)((KEY_ELEMS + W_ELEMS) / 4 / 256), 256>>>(keys, Wm);
    conv_qt<<<dim3(NJ / 64, DDIM / 32, BATCH), 256>>>(queries);

    k_hm1<<<dim3(NJ / 128, LSEQ / 128, BATCH), 256, SMEM_BYTES>>>();
    k_softmax<<<MROWS, 320>>>(qmask, kmask);
    k_hm2<<<dim3(DDIM / 128, LSEQ / 128, BATCH), 256, SMEM_BYTES>>>(keys);
    k_hm3<<<dim3(DDIM / 128, MROWS / 128, 1), 256, SMEM_BYTES>>>(bias, out);
}

// round 16
// speedup vs baseline: 1.0351x; 1.0014x over previous
#include <cuda_runtime.h>
#include <cuda_bf16.h>
#include <stdint.h>
#include <math.h>

// Shapes
#define BATCH 32
#define NTURN 20
#define JTOK  64
#define LSEQ  256
#define DDIM  512
#define NJ    1280
#define MROWS 8192
#define NEGV  (-4294967295.0f)

// Compact split scratch (hi/lo)
__device__ __align__(16) __nv_bfloat16 g_Khi [(size_t)BATCH*LSEQ*DDIM];
__device__ __align__(16) __nv_bfloat16 g_Klo [(size_t)BATCH*LSEQ*DDIM];
__device__ __align__(16) __nv_bfloat16 g_Qhi [(size_t)BATCH*NJ*DDIM];
__device__ __align__(16) __nv_bfloat16 g_Qlo [(size_t)BATCH*NJ*DDIM];
__device__ __align__(16) __nv_bfloat16 g_Qthi[(size_t)BATCH*DDIM*NJ];   // transposed [b][d][j]
__device__ __align__(16) __nv_bfloat16 g_Qtlo[(size_t)BATCH*DDIM*NJ];
__device__ __align__(16) float         g_S   [(size_t)BATCH*LSEQ*NJ];
__device__ __align__(16) __nv_bfloat16 g_Chi [(size_t)BATCH*LSEQ*NJ];
__device__ __align__(16) __nv_bfloat16 g_Clo [(size_t)BATCH*LSEQ*NJ];
__device__ __align__(16) __nv_bfloat16 g_Fhi [(size_t)MROWS*1024];
__device__ __align__(16) __nv_bfloat16 g_Flo [(size_t)MROWS*1024];
__device__ __align__(16) __nv_bfloat16 g_Whi [(size_t)DDIM*1024];
__device__ __align__(16) __nv_bfloat16 g_Wlo [(size_t)DDIM*1024];

#define KEY_ELEMS ((size_t)BATCH*LSEQ*DDIM)   // 4,194,304
#define W_ELEMS   ((size_t)DDIM*1024)         //   524,288

// ---------------------------------------------------------------------------
// helpers
// ---------------------------------------------------------------------------
__device__ __forceinline__ uint32_t smem_u32(const void* p) {
    uint32_t a;
    asm("{ .reg .u64 t; cvta.to.shared.u64 t, %1; cvt.u32.u64 %0, t; }" : "=r"(a) : "l"(p));
    return a;
}
__device__ __forceinline__ void split_bf(float x, __nv_bfloat16& h, __nv_bfloat16& l) {
    h = __float2bfloat16(x);
    l = __float2bfloat16(x - __bfloat162float(h));
}
__device__ __forceinline__ void cpa16(uint32_t saddr, const void* g) {
    asm volatile("cp.async.cg.shared.global [%0], [%1], 16;" :: "r"(saddr), "l"(g));
}
#define CP_COMMIT() asm volatile("cp.async.commit_group;")
#define CP_WAIT0()  asm volatile("cp.async.wait_group 0;")

#define LDSM4(R, ADDR) \
    asm volatile("ldmatrix.sync.aligned.m8n8.x4.shared.b16 {%0,%1,%2,%3}, [%4];" \
        : "=r"((R)[0]), "=r"((R)[1]), "=r"((R)[2]), "=r"((R)[3]) : "r"(ADDR))

#define MMA16816(C, A, B0, B1) \
    asm volatile("mma.sync.aligned.m16n8k16.row.col.f32.bf16.bf16.f32 " \
        "{%0,%1,%2,%3},{%4,%5,%6,%7},{%8,%9},{%0,%1,%2,%3};" \
        : "+f"((C)[0]), "+f"((C)[1]), "+f"((C)[2]), "+f"((C)[3]) \
        : "r"((A)[0]), "r"((A)[1]), "r"((A)[2]), "r"((A)[3]), "r"(B0), "r"(B1))

// smem: 2 stages x 4 tiles (A_hi, A_lo, B_hi, B_lo); tile = 128 rows x 32 K-cols
#define PITCH 40
#define TILE  (128 * PITCH * 2)           // 10240 B
#define STG   (4 * TILE)                  // 40960 B per stage
#define SMEM_BYTES (2 * STG)              // 81920 B (2 CTAs/SM = 160KB)

// ---------------------------------------------------------------------------
// load one K=32 chunk: 4 tiles (A_hi, A_lo, B_hi, B_lo)
// ---------------------------------------------------------------------------
__device__ __forceinline__ void load_tiles4(uint32_t sb, int stage,
                                            const __nv_bfloat16* Ah, const __nv_bfloat16* Al, int lda,
                                            const __nv_bfloat16* Bh, const __nv_bfloat16* Bl, int ldb,
                                            int koff)
{
    const int tid = threadIdx.x;
    const uint32_t s0 = sb + stage * STG;
    #pragma unroll
    for (int i = 0; i < 2; ++i) {
        int id = tid + i * 256;
        int r = id >> 2, cc = id & 3;
        uint32_t so = (uint32_t)(r * PITCH + cc * 8) * 2;
        size_t goA = (size_t)r * lda + koff + cc * 8;
        size_t goB = (size_t)r * ldb + koff + cc * 8;
        cpa16(s0 + so,            Ah + goA);
        cpa16(s0 + TILE + so,     Al + goA);
        cpa16(s0 + 2 * TILE + so, Bh + goB);
        cpa16(s0 + 3 * TILE + so, Bl + goB);
    }
}

// per K=32 chunk: 2 k16 steps; per mt: load a_hi/a_lo frags, then issue the
// three products in separate nt-sweeps so same-accumulator MMAs are 4 apart.
__device__ __forceinline__ void hmma_compute4(uint32_t sb, int stage,
                                              int lane, int wm0, int wn0,
                                              float acc[4][4][4])
{
    const uint32_t sAh = sb + stage * STG;
    const uint32_t sAl = sAh + TILE;
    const uint32_t sBh = sAh + 2 * TILE;
    const uint32_t sBl = sAh + 3 * TILE;
    const int rowoff = lane & 15;
    #pragma unroll
    for (int ks = 0; ks < 2; ++ks) {
        const int coloff = ks * 16 + (lane >> 4) * 8;
        uint32_t bh[2][4], blo[2][4];
        #pragma unroll
        for (int np = 0; np < 2; ++np) {
            uint32_t bo = (uint32_t)((wn0 + np * 16 + rowoff) * PITCH + coloff) * 2;
            LDSM4(bh[np],  sBh + bo);
            LDSM4(blo[np], sBl + bo);
        }
        #pragma unroll
        for (int mt = 0; mt < 4; ++mt) {
            uint32_t ah[4], al[4];
            uint32_t ao = (uint32_t)((wm0 + mt * 16 + rowoff) * PITCH + coloff) * 2;
            LDSM4(ah, sAh + ao);
            LDSM4(al, sAl + ao);
            #pragma unroll
            for (int nt = 0; nt < 4; ++nt)
                MMA16816(acc[mt][nt], ah, bh[nt >> 1][nt & 1],  bh[nt >> 1][2 + (nt & 1)]);
            #pragma unroll
            for (int nt = 0; nt < 4; ++nt)
                MMA16816(acc[mt][nt], ah, blo[nt >> 1][nt & 1], blo[nt >> 1][2 + (nt & 1)]);
            #pragma unroll
            for (int nt = 0; nt < 4; ++nt)
                MMA16816(acc[mt][nt], al, bh[nt >> 1][nt & 1],  bh[nt >> 1][2 + (nt & 1)]);
        }
    }
}

// 2-stage pipelined mainloop over bl K=32 chunks; one __syncthreads per chunk.
__device__ __forceinline__ void hmma_loop4(char* smem,
                                           const __nv_bfloat16* Ahi, const __nv_bfloat16* Alo, int lda,
                                           const __nv_bfloat16* Bhi, const __nv_bfloat16* Blo, int ldb,
                                           int bl, float acc[4][4][4])
{
    const int tid = threadIdx.x;
    const int lane = tid & 31, wid = tid >> 5;
    const int wm0 = (wid >> 2) * 64, wn0 = (wid & 3) * 32;
    const uint32_t sb = smem_u32(smem);

    load_tiles4(sb, 0, Ahi, Alo, lda, Bhi, Blo, ldb, 0);
    CP_COMMIT();

    for (int c = 0; c < bl; ++c) {
        CP_WAIT0();
        __syncthreads();
        if (c + 1 < bl) {
            load_tiles4(sb, (c + 1) & 1, Ahi, Alo, lda, Bhi, Blo, ldb, (c + 1) * 32);
            CP_COMMIT();
        }
        hmma_compute4(sb, c & 1, lane, wm0, wn0, acc);
    }
}

// ---------------------------------------------------------------------------
// Conversion kernels (fp32 -> compact hi/lo bf16)
// ---------------------------------------------------------------------------
__device__ __forceinline__ void split4_store(const float4 v, __nv_bfloat16* hi, __nv_bfloat16* lo, size_t o)
{
    __nv_bfloat16 h[4], l[4];
    split_bf(v.x, h[0], l[0]); split_bf(v.y, h[1], l[1]);
    split_bf(v.z, h[2], l[2]); split_bf(v.w, h[3], l[3]);
    __nv_bfloat162 hh0, hh1, ll0, ll1;
    hh0.x = h[0]; hh0.y = h[1]; hh1.x = h[2]; hh1.y = h[3];
    ll0.x = l[0]; ll0.y = l[1]; ll1.x = l[2]; ll1.y = l[3];
    *(__nv_bfloat162*)(hi + o) = hh0; *(__nv_bfloat162*)(hi + o + 2) = hh1;
    *(__nv_bfloat162*)(lo + o) = ll0; *(__nv_bfloat162*)(lo + o + 2) = ll1;
}

// keys + W split in one kernel (flat index over both tensors / 4 elems)
__global__ __launch_bounds__(256) void conv_kw(const float* __restrict__ keys,
                                               const float* __restrict__ Wm)
{
    size_t t = (size_t)blockIdx.x * 256 + threadIdx.x;
    size_t o = t * 4;
    if (o < KEY_ELEMS) {
        split4_store(*(const float4*)(keys + o), g_Khi, g_Klo, o);
    } else {
        size_t ow = o - KEY_ELEMS;
        split4_store(*(const float4*)(Wm + ow), g_Whi, g_Wlo, ow);
    }
}

// Merged split + transpose: q[b][j][d] -> Q{hi,lo}[b][j][d] AND Qt{hi,lo}[b][d][j].
__global__ __launch_bounds__(256) void conv_qt(const float* __restrict__ q)
{
    __shared__ __nv_bfloat16 shh[32][72];
    __shared__ __nv_bfloat16 shl[32][72];
    const int b  = blockIdx.z;
    const int d0 = blockIdx.y * 32;
    const int j0 = blockIdx.x * 64;
    const int t  = threadIdx.x;

    #pragma unroll
    for (int i = 0; i < 2; ++i) {
        int jj = (t >> 3) + i * 32;               // 0..63
        int dd = (t & 7) * 4;                     // 0..28
        size_t qo = ((size_t)b * NJ + j0 + jj) * DDIM + d0 + dd;
        float4 v = *(const float4*)(q + qo);
        __nv_bfloat16 h0, l0, h1, l1, h2, l2, h3, l3;
        split_bf(v.x, h0, l0); split_bf(v.y, h1, l1);
        split_bf(v.z, h2, l2); split_bf(v.w, h3, l3);
        __nv_bfloat162 hp0, hp1, lp0, lp1;
        hp0.x = h0; hp0.y = h1; hp1.x = h2; hp1.y = h3;
        lp0.x = l0; lp0.y = l1; lp1.x = l2; lp1.y = l3;
        *(__nv_bfloat162*)(g_Qhi + qo)     = hp0; *(__nv_bfloat162*)(g_Qhi + qo + 2) = hp1;
        *(__nv_bfloat162*)(g_Qlo + qo)     = lp0; *(__nv_bfloat162*)(g_Qlo + qo + 2) = lp1;
        shh[dd+0][jj] = h0; shl[dd+0][jj] = l0;
        shh[dd+1][jj] = h1; shl[dd+1][jj] = l1;
        shh[dd+2][jj] = h2; shl[dd+2][jj] = l2;
        shh[dd+3][jj] = h3; shl[dd+3][jj] = l3;
    }
    __syncthreads();

    const int r  = t >> 3;                        // 0..31 (d row)
    const int pc = t & 7;                         // 8 bf16 = 16B chunk
    size_t o = ((size_t)b * DDIM + d0 + r) * NJ + j0 + pc * 8;
    *(uint4*)(g_Qthi + o) = *(const uint4*)&shh[r][pc * 8];
    *(uint4*)(g_Qtlo + o) = *(const uint4*)&shl[r][pc * 8];
}

// ---------------------------------------------------------------------------
// GEMM1: scores[b] = keys x queries^T  (M=256, N=1280, K=512) -> g_S
// ---------------------------------------------------------------------------
__global__ __launch_bounds__(256, 2) void k_hm1()
{
    extern __shared__ char smem[];
    const int b = blockIdx.z, m0 = blockIdx.y * 128, n0 = blockIdx.x * 128;
    const __nv_bfloat16* Ah = g_Khi + ((size_t)b * LSEQ + m0) * DDIM;
    const __nv_bfloat16* Al = g_Klo + ((size_t)b * LSEQ + m0) * DDIM;
    const __nv_bfloat16* Bh = g_Qhi + ((size_t)b * NJ + n0) * DDIM;
    const __nv_bfloat16* Bl = g_Qlo + ((size_t)b * NJ + n0) * DDIM;
    float acc[4][4][4] = {};
    hmma_loop4(smem, Ah, Al, DDIM, Bh, Bl, DDIM, DDIM / 32, acc);

    const int lane = threadIdx.x & 31, wid = threadIdx.x >> 5;
    const int wm0 = (wid >> 2) * 64, wn0 = (wid & 3) * 32;
    float* C = g_S + (size_t)b * LSEQ * NJ;
    #pragma unroll
    for (int mt = 0; mt < 4; ++mt)
        #pragma unroll
        for (int nt = 0; nt < 4; ++nt)
            #pragma unroll
            for (int rh = 0; rh < 2; ++rh) {
                int m = m0 + wm0 + mt * 16 + (lane >> 2) + rh * 8;
                int n = n0 + wn0 + nt * 8 + (lane & 3) * 2;
                *(float2*)(C + (size_t)m * NJ + n) =
                    make_float2(acc[mt][nt][rh * 2], acc[mt][nt][rh * 2 + 1]);
            }
}

// ---------------------------------------------------------------------------
// Softmax + combined weights -> g_Chi / g_Clo  (register-resident)
// 320 threads = 10 warps x 2 turns; lanes hold p-values in regs across the
// inter-warp turn-softmax exchange; only sim2/tvalid/wn go through smem.
// ---------------------------------------------------------------------------
__global__ __launch_bounds__(320) void k_softmax(const float* __restrict__ qmask,
                                                 const float* __restrict__ kmask)
{
    const int row = blockIdx.x;
    const int b   = row >> 8;

    __shared__ float sim2[32];
    __shared__ uint32_t tvalid[32];
    __shared__ float wn[NTURN];

    const int tid = threadIdx.x;
    const int wid = tid >> 5, lane = tid & 31;
    const float* srow = g_S + (size_t)row * NJ;
    const float* qmrow = qmask + b * NJ;

    float p1[2], p2[2];
    #pragma unroll
    for (int rep = 0; rep < 2; ++rep) {
        const int n = wid + rep * 10;
        const int base = n * JTOK;
        float q1 = qmrow[base + lane],  q2 = qmrow[base + 32 + lane];
        float s1 = srow[base + lane],   s2 = srow[base + 32 + lane];
        float x1 = (q1 == 0.0f) ? NEGV : s1;
        float x2 = (q2 == 0.0f) ? NEGV : s2;
        float mx = fmaxf(x1, x2);
        #pragma unroll
        for (int o = 16; o; o >>= 1) mx = fmaxf(mx, __shfl_xor_sync(0xFFFFFFFFu, mx, o));
        float e1 = __expf(x1 - mx), e2 = __expf(x2 - mx);
        float es = e1 + e2, sp = e1 * s1 + e2 * s2;
        #pragma unroll
        for (int o = 16; o; o >>= 1) {
            es += __shfl_xor_sync(0xFFFFFFFFu, es, o);
            sp += __shfl_xor_sync(0xFFFFFFFFu, sp, o);
        }
        uint32_t vb = __ballot_sync(0xFFFFFFFFu, (q1 != 0.0f) || (q2 != 0.0f));
        float inv = 1.0f / es;
        p1[rep] = e1 * inv;
        p2[rep] = e2 * inv;
        if (lane == 0) { sim2[n] = sp * inv; tvalid[n] = vb; }
    }
    __syncthreads();

    if (wid == 0) {
        float v = (lane < NTURN && tvalid[lane]) ? sim2[lane] : NEGV;
        float mx = v;
        #pragma unroll
        for (int o = 16; o; o >>= 1) mx = fmaxf(mx, __shfl_xor_sync(0xFFFFFFFFu, mx, o));
        float e = (lane < NTURN) ? __expf(v - mx) : 0.0f;
        float es = e;
        #pragma unroll
        for (int o = 16; o; o >>= 1) es += __shfl_xor_sync(0xFFFFFFFFu, es, o);
        if (lane < NTURN) wn[lane] = e / es;
    }
    __syncthreads();

    const float m = kmask[row];
    __nv_bfloat16* chi = g_Chi + (size_t)row * NJ;
    __nv_bfloat16* clo = g_Clo + (size_t)row * NJ;
    #pragma unroll
    for (int rep = 0; rep < 2; ++rep) {
        const int n = wid + rep * 10;
        const int base = n * JTOK;
        const float w = m * wn[n];
        __nv_bfloat16 h, l;
        split_bf(w * p1[rep], h, l);
        chi[base + lane] = h;  clo[base + lane] = l;
        split_bf(w * p2[rep], h, l);
        chi[base + 32 + lane] = h;  clo[base + 32 + lane] = l;
    }
}

// ---------------------------------------------------------------------------
// GEMM2: attn[b] = C x queries (M=256, N=512, K=1280) -> g_Fhi/g_Flo
// ---------------------------------------------------------------------------
__global__ __launch_bounds__(256, 2) void k_hm2(const float* __restrict__ keys)
{
    extern __shared__ char smem[];
    const int b = blockIdx.z, m0 = blockIdx.y * 128, n0 = blockIdx.x * 128;
    const __nv_bfloat16* Ah = g_Chi  + ((size_t)b * LSEQ + m0) * NJ;
    const __nv_bfloat16* Al = g_Clo  + ((size_t)b * LSEQ + m0) * NJ;
    const __nv_bfloat16* Bh = g_Qthi + ((size_t)b * DDIM + n0) * NJ;
    const __nv_bfloat16* Bl = g_Qtlo + ((size_t)b * DDIM + n0) * NJ;
    float acc[4][4][4] = {};
    hmma_loop4(smem, Ah, Al, NJ, Bh, Bl, NJ, NJ / 32, acc);

    const int lane = threadIdx.x & 31, wid = threadIdx.x >> 5;
    const int wm0 = (wid >> 2) * 64, wn0 = (wid & 3) * 32;
    const float* keyb = keys + (size_t)b * LSEQ * DDIM;
    #pragma unroll
    for (int mt = 0; mt < 4; ++mt)
        #pragma unroll
        for (int nt = 0; nt < 4; ++nt)
            #pragma unroll
            for (int rh = 0; rh < 2; ++rh) {
                int m = m0 + wm0 + mt * 16 + (lane >> 2) + rh * 8;
                int n = n0 + wn0 + nt * 8 + (lane & 3) * 2;
                float a0 = acc[mt][nt][rh * 2], a1 = acc[mt][nt][rh * 2 + 1];
                float2 kv = *(const float2*)(keyb + (size_t)m * DDIM + n);
                float mu0 = a0 * kv.x, mu1 = a1 * kv.y;
                float df0 = a0 - kv.x, df1 = a1 - kv.y;
                float sq0 = df0 * df0, sq1 = df1 * df1;
                size_t rowo = ((size_t)b * LSEQ + m) * 1024;
                __nv_bfloat16 h0, l0, h1, l1;
                __nv_bfloat162 hp, lp;
                split_bf(mu0, h0, l0); split_bf(mu1, h1, l1);
                hp.x = h0; hp.y = h1; lp.x = l0; lp.y = l1;
                *(__nv_bfloat162*)(g_Fhi + rowo + n) = hp;
                *(__nv_bfloat162*)(g_Flo + rowo + n) = lp;
                split_bf(sq0, h0, l0); split_bf(sq1, h1, l1);
                hp.x = h0; hp.y = h1; lp.x = l0; lp.y = l1;
                *(__nv_bfloat162*)(g_Fhi + rowo + 512 + n) = hp;
                *(__nv_bfloat162*)(g_Flo + rowo + 512 + n) = lp;
            }
}

// ---------------------------------------------------------------------------
// GEMM3: out = relu(F x W^T + b)  (M=8192, N=512, K=1024)
// ---------------------------------------------------------------------------
__global__ __launch_bounds__(256, 2) void k_hm3(const float* __restrict__ bias,
                                                float* __restrict__ out)
{
    extern __shared__ char smem[];
    const int m0 = blockIdx.y * 128, n0 = blockIdx.x * 128;
    const __nv_bfloat16* Ah = g_Fhi + (size_t)m0 * 1024;
    const __nv_bfloat16* Al = g_Flo + (size_t)m0 * 1024;
    const __nv_bfloat16* Bh = g_Whi + (size_t)n0 * 1024;
    const __nv_bfloat16* Bl = g_Wlo + (size_t)n0 * 1024;
    float acc[4][4][4] = {};
    hmma_loop4(smem, Ah, Al, 1024, Bh, Bl, 1024, 1024 / 32, acc);

    const int lane = threadIdx.x & 31, wid = threadIdx.x >> 5;
    const int wm0 = (wid >> 2) * 64, wn0 = (wid & 3) * 32;
    #pragma unroll
    for (int mt = 0; mt < 4; ++mt)
        #pragma unroll
        for (int nt = 0; nt < 4; ++nt)
            #pragma unroll
            for (int rh = 0; rh < 2; ++rh) {
                int m = m0 + wm0 + mt * 16 + (lane >> 2) + rh * 8;
                int n = n0 + wn0 + nt * 8 + (lane & 3) * 2;
                float2 bb = *(const float2*)(bias + n);
                float v0 = fmaxf(acc[mt][nt][rh * 2]     + bb.x, 0.0f);
                float v1 = fmaxf(acc[mt][nt][rh * 2 + 1] + bb.y, 0.0f);
                *(float2*)(out + (size_t)m * DDIM + n) = make_float2(v0, v1);
            }
}

// ---------------------------------------------------------------------------
extern "C" void kernel_launch(void* const* d_in, const int* in_sizes, int n_in,
                              void* d_out, int out_size)
{
    const float* queries = (const float*)d_in[0];  // [32,20,64,512]
    const float* keys    = (const float*)d_in[1];  // [32,256,512]
    const float* qmask   = (const float*)d_in[2];  // [32,20,64]
    const float* kmask   = (const float*)d_in[3];  // [32,256]
    const float* Wm      = (const float*)d_in[4];  // [512,1024]
    const float* bias    = (const float*)d_in[5];  // [512]
    float* out = (float*)d_out;                    // [32,256,512]

    cudaFuncSetAttribute(k_hm1, cudaFuncAttributeMaxDynamicSharedMemorySize, SMEM_BYTES);
    cudaFuncSetAttribute(k_hm2, cudaFuncAttributeMaxDynamicSharedMemorySize, SMEM_BYTES);
    cudaFuncSetAttribute(k_hm3, cudaFuncAttributeMaxDynamicSharedMemorySize, SMEM_BYTES);

    conv_kw<<<(int)((KEY_ELEMS + W_ELEMS) / 4 / 256), 256>>>(keys, Wm);
    conv_qt<<<dim3(NJ / 64, DDIM / 32, BATCH), 256>>>(queries);

    k_hm1<<<dim3(NJ / 128, LSEQ / 128, BATCH), 256, SMEM_BYTES>>>();
    k_softmax<<<MROWS, 320>>>(qmask, kmask);
    k_hm2<<<dim3(DDIM / 128, LSEQ / 128, BATCH), 256, SMEM_BYTES>>>(keys);
    k_hm3<<<dim3(DDIM / 128, MROWS / 128, 1), 256, SMEM_BYTES>>>(bias, out);
}